// round 1
// baseline (speedup 1.0000x reference)
#include <cuda_runtime.h>
#include <math.h>

#define BB 16
#define TT 1024
#define IND 64
#define OUTD 64
#define HHD 512
#define NND 128
#define MMD 40
#define KTOT 616      // IND + MMD + HHD
#define KPAD 628      // padded row stride (floats), 157 float4, good bank spread
#define KP4  157
#define NCTA 128
#define NTHR 256
#define HPER 4        // h indices owned per CTA (512/128)
#define EPSV 1e-8f
#define PROJ_EXTRA 57 // 185 - 128

// ---------------- persistent global state ----------------
__device__ __align__(16) float g_h[2][BB][HHD];
__device__ __align__(16) float g_r[2][BB][MMD];
__device__ __align__(16) float g_key[BB][MMD];
__device__ __align__(16) float g_e[BB][MMD];
__device__ __align__(16) float g_a[BB][MMD];
__device__ float g_beta[BB];

__device__ unsigned g_cnt = 0;
__device__ volatile unsigned g_epoch = 0;

// Sense-free grid barrier: read epoch, arrive, last arriver resets count and
// bumps epoch; others spin on change. Epoch is only compared for inequality,
// so its absolute value across launches is irrelevant (state stays consistent:
// count always returns to 0).
__device__ __forceinline__ void grid_barrier() {
    __syncthreads();
    if (threadIdx.x == 0) {
        unsigned old = g_epoch;                  // must read BEFORE arriving
        __threadfence();
        if (atomicAdd(&g_cnt, 1u) == NCTA - 1u) {
            atomicExch(&g_cnt, 0u);
            __threadfence();
            atomicAdd((unsigned*)&g_epoch, 1u);
        } else {
            while (g_epoch == old) { }
        }
        __threadfence();
    }
    __syncthreads();
}

struct __align__(16) Smem {
    float W[16 * KPAD];     // this CTA's 16 gate rows, [x|r|h] concat, padded
    float inp[BB * KPAD];   // staged [x_t, r, h] per batch, padded
    float red[4 * 64 * 4];  // split-K partial sums
    float gate[16 * BB];    // assembled gate pre-activations
    float bias[16];         // b_ih + b_hh for owned rows
    float cst[BB * HPER];   // persistent cell state slice c[b][jl]
    float mem[NND * 41];    // NTM memory (CTAs 0..15 only), padded stride
    float key[MMD];
    float ev[MMD];
    float av[MMD];
    float z[NND];
    float w[NND];
    float rsc[16];
    float scal[4];          // [0]=||key||+eps, [1]=beta
};

__device__ __forceinline__ const float* proj_w(int row,
    const float* W_fc, const float* W_k, const float* W_b,
    const float* W_e, const float* W_a)
{
    if (row < 64)   return W_fc + row * HHD;
    if (row < 104)  return W_k + (row - 64) * HHD;
    if (row == 104) return W_b;
    if (row < 145)  return W_e + (row - 105) * HHD;
    return W_a + (row - 145) * HHD;
}

__device__ __forceinline__ void apply_proj(int row, float v, int b, int t,
    float* out_O, const float* b_fc, const float* b_k, const float* b_b,
    const float* b_e, const float* b_a)
{
    if (row < 64) {
        out_O[(b * TT + t) * OUTD + row] = tanhf(v + b_fc[row]);
    } else if (row < 104) {
        g_key[b][row - 64] = tanhf(v + b_k[row - 64]);
    } else if (row == 104) {
        float zz = v + b_b[0];
        // softplus(x) = max(x,0) + log1p(exp(-|x|))
        g_beta[b] = fmaxf(zz, 0.f) + log1pf(expf(-fabsf(zz))) + EPSV;
    } else if (row < 145) {
        int m = row - 105;
        g_e[b][m] = 1.f / (1.f + expf(-(v + b_e[m])));
    } else {
        int m = row - 145;
        g_a[b][m] = tanhf(v + b_a[m]);
    }
}

__global__ void __launch_bounds__(NTHR, 1) ntm_kernel(
    const float* __restrict__ x,    const float* __restrict__ h0,
    const float* __restrict__ c0,   const float* __restrict__ mem0,
    const float* __restrict__ r0_,  const float* __restrict__ W_ih,
    const float* __restrict__ b_ih, const float* __restrict__ W_hh,
    const float* __restrict__ b_hh, const float* __restrict__ W_fc,
    const float* __restrict__ b_fc, const float* __restrict__ W_e,
    const float* __restrict__ b_e,  const float* __restrict__ W_a,
    const float* __restrict__ b_a,  const float* __restrict__ W_k,
    const float* __restrict__ b_k,  const float* __restrict__ W_b,
    const float* __restrict__ b_b,  float* __restrict__ out)
{
    extern __shared__ unsigned char smem_raw[];
    Smem& s = *reinterpret_cast<Smem*>(smem_raw);
    const int cta = blockIdx.x;
    const int tid = threadIdx.x;
    const int j0 = cta * HPER;

    float* out_O = out;
    float* out_h = out + (size_t)BB * TT * OUTD;
    float* out_c = out_h + BB * HHD;

    // ---------------- init: load persistent weights & state ----------------
    for (int idx = tid; idx < 16 * KPAD; idx += NTHR) {
        int lrow = idx / KPAD, k = idx - lrow * KPAD;
        int gate = lrow >> 2, jl = lrow & 3;
        int gr = gate * HHD + j0 + jl;
        float v = 0.f;
        if (k < IND + MMD)      v = W_ih[gr * (IND + MMD) + k];
        else if (k < KTOT)      v = W_hh[gr * HHD + (k - (IND + MMD))];
        s.W[idx] = v;
    }
    if (tid < 16) {
        int gate = tid >> 2, jl = tid & 3;
        int gr = gate * HHD + j0 + jl;
        s.bias[tid] = b_ih[gr] + b_hh[gr];
    }
    if (tid < BB * HPER) {
        int b = tid >> 2, jl = tid & 3;
        g_h[0][b][j0 + jl] = h0[b * HHD + j0 + jl];
        s.cst[tid] = c0[b * HHD + j0 + jl];
    }
    if (cta == 0) {
        float* gr0 = &g_r[0][0][0];
        for (int i = tid; i < BB * MMD; i += NTHR) gr0[i] = r0_[i];
    }
    if (cta < BB) {
        for (int idx = tid; idx < NND * MMD; idx += NTHR) {
            int n = idx / MMD, m = idx - n * MMD;
            s.mem[n * 41 + m] = mem0[cta * NND * MMD + idx];
        }
    }
    grid_barrier();

    const int kc = tid >> 6;          // split-K chunk 0..3
    const int tile = tid & 63;        // 2x2 tile id
    const int rp = tile & 7;          // row pair 0..7
    const int bp = tile >> 3;         // batch pair 0..7

    for (int t = 0; t < TT; t++) {
        const int pin = t & 1, pout = pin ^ 1;

        // ========== Phase 1: gates GEMM + LSTM pointwise ==========
        for (int idx = tid; idx < BB * KPAD; idx += NTHR) {
            int b = idx / KPAD, k = idx - b * KPAD;
            float v = 0.f;
            if (k < IND)            v = x[(b * TT + t) * IND + k];
            else if (k < IND + MMD) v = g_r[pin][b][k - IND];
            else if (k < KTOT)      v = g_h[pin][b][k - (IND + MMD)];
            s.inp[idx] = v;
        }
        __syncthreads();
        {
            const float4* W4 = reinterpret_cast<const float4*>(s.W);
            const float4* I4 = reinterpret_cast<const float4*>(s.inp);
            const float4* w0p = W4 + (2 * rp) * KP4 + kc * 39;
            const float4* w1p = w0p + KP4;
            const float4* i0p = I4 + (2 * bp) * KP4 + kc * 39;
            const float4* i1p = i0p + KP4;
            float a00 = 0.f, a01 = 0.f, a10 = 0.f, a11 = 0.f;
            #pragma unroll 13
            for (int q = 0; q < 39; q++) {
                float4 wa = w0p[q], wb = w1p[q], ia = i0p[q], ib = i1p[q];
                a00 += wa.x * ia.x; a00 += wa.y * ia.y; a00 += wa.z * ia.z; a00 += wa.w * ia.w;
                a01 += wa.x * ib.x; a01 += wa.y * ib.y; a01 += wa.z * ib.z; a01 += wa.w * ib.w;
                a10 += wb.x * ia.x; a10 += wb.y * ia.y; a10 += wb.z * ia.z; a10 += wb.w * ia.w;
                a11 += wb.x * ib.x; a11 += wb.y * ib.y; a11 += wb.z * ib.z; a11 += wb.w * ib.w;
            }
            float* rb = &s.red[(kc * 64 + tile) * 4];
            rb[0] = a00; rb[1] = a01; rb[2] = a10; rb[3] = a11;
        }
        __syncthreads();
        {
            int lrow = tid & 15, b = tid >> 4;
            int tl = (b >> 1) * 8 + (lrow >> 1);
            int j = (lrow & 1) * 2 + (b & 1);
            float v = s.bias[lrow];
            v += s.red[(0 * 64 + tl) * 4 + j];
            v += s.red[(1 * 64 + tl) * 4 + j];
            v += s.red[(2 * 64 + tl) * 4 + j];
            v += s.red[(3 * 64 + tl) * 4 + j];
            s.gate[lrow * BB + b] = v;
        }
        __syncthreads();
        if (tid < BB * HPER) {
            int b = tid >> 2, jl = tid & 3;
            float gi = s.gate[(0 * 4 + jl) * BB + b];
            float gf = s.gate[(1 * 4 + jl) * BB + b];
            float gg = s.gate[(2 * 4 + jl) * BB + b];
            float go = s.gate[(3 * 4 + jl) * BB + b];
            float iv = 1.f / (1.f + expf(-gi));
            float fv = 1.f / (1.f + expf(-gf));
            float gv = tanhf(gg);
            float ov = 1.f / (1.f + expf(-go));
            float cn = fv * s.cst[tid] + iv * gv;
            float hn = ov * tanhf(cn);
            s.cst[tid] = cn;
            g_h[pout][b][j0 + jl] = hn;
            if (t == TT - 1) {
                out_h[b * HHD + j0 + jl] = hn;
                out_c[b * HHD + j0 + jl] = cn;
            }
        }
        grid_barrier();

        // ========== Phase 2: projection rows (fc / key / beta / e / a) ==========
        {
            int b = tid >> 4, kcc = tid & 15;
            const float4* h4 =
                reinterpret_cast<const float4*>(&g_h[pout][b][0]) + kcc * 8;
            int row0 = cta;
            bool two = (cta < PROJ_EXTRA);
            const float* w0 = proj_w(row0, W_fc, W_k, W_b, W_e, W_a);
            const float* w1 = two ? proj_w(row0 + NCTA, W_fc, W_k, W_b, W_e, W_a)
                                  : w0;
            const float4* w04 = reinterpret_cast<const float4*>(w0) + kcc * 8;
            const float4* w14 = reinterpret_cast<const float4*>(w1) + kcc * 8;
            float acc0 = 0.f, acc1 = 0.f;
            #pragma unroll
            for (int q = 0; q < 8; q++) {
                float4 hv = h4[q];
                float4 wv = w04[q];
                acc0 += wv.x * hv.x; acc0 += wv.y * hv.y;
                acc0 += wv.z * hv.z; acc0 += wv.w * hv.w;
                float4 wv1 = w14[q];
                acc1 += wv1.x * hv.x; acc1 += wv1.y * hv.y;
                acc1 += wv1.z * hv.z; acc1 += wv1.w * hv.w;
            }
            #pragma unroll
            for (int off = 8; off; off >>= 1) {
                acc0 += __shfl_xor_sync(0xffffffffu, acc0, off);
                acc1 += __shfl_xor_sync(0xffffffffu, acc1, off);
            }
            if (kcc == 0) {
                apply_proj(row0, acc0, b, t, out_O, b_fc, b_k, b_b, b_e, b_a);
                if (two)
                    apply_proj(row0 + NCTA, acc1, b, t, out_O, b_fc, b_k, b_b, b_e, b_a);
            }
        }
        grid_barrier();

        // ========== Phase 3: content addressing + memory write + read ==========
        if (cta < BB) {
            const int b = cta;
            if (tid < MMD) {
                s.key[tid] = g_key[b][tid];
                s.ev[tid]  = g_e[b][tid];
                s.av[tid]  = g_a[b][tid];
            }
            if (tid == 0) s.scal[1] = g_beta[b];
            __syncthreads();
            if (tid < 32) {
                float v = 0.f;
                if (tid < MMD)      { float kv = s.key[tid];      v  = kv * kv; }
                if (tid + 32 < MMD) { float kv = s.key[tid + 32]; v += kv * kv; }
                #pragma unroll
                for (int off = 16; off; off >>= 1)
                    v += __shfl_xor_sync(0xffffffffu, v, off);
                if (tid == 0) s.scal[0] = sqrtf(v) + EPSV;
            }
            __syncthreads();
            if (tid < NND) {
                const float* mr = &s.mem[tid * 41];
                float dot = 0.f, nrm = 0.f;
                #pragma unroll
                for (int m = 0; m < MMD; m++) {
                    float mv = mr[m];
                    dot += mv * s.key[m];
                    nrm += mv * mv;
                }
                float sim = dot / ((sqrtf(nrm) + EPSV) * s.scal[0]);
                s.z[tid] = s.scal[1] * sim;
            }
            __syncthreads();
            float zl = (tid < NND) ? s.z[tid] : 0.f;
            if (tid < NND) {
                float mv = zl;
                #pragma unroll
                for (int off = 16; off; off >>= 1)
                    mv = fmaxf(mv, __shfl_xor_sync(0xffffffffu, mv, off));
                if ((tid & 31) == 0) s.rsc[tid >> 5] = mv;
            }
            __syncthreads();
            if (tid < NND) {
                float gmax = fmaxf(fmaxf(s.rsc[0], s.rsc[1]),
                                   fmaxf(s.rsc[2], s.rsc[3]));
                float ee = expf(zl - gmax);
                s.w[tid] = ee;
                float sv = ee;
                #pragma unroll
                for (int off = 16; off; off >>= 1)
                    sv += __shfl_xor_sync(0xffffffffu, sv, off);
                if ((tid & 31) == 0) s.rsc[4 + (tid >> 5)] = sv;
            }
            __syncthreads();
            if (tid < NND) {
                float tot = s.rsc[4] + s.rsc[5] + s.rsc[6] + s.rsc[7];
                float wv = s.w[tid] / tot;
                s.w[tid] = wv;
                float* mr = &s.mem[tid * 41];
                #pragma unroll
                for (int m = 0; m < MMD; m++)
                    mr[m] = mr[m] * (1.f - wv * s.ev[m]) + wv * s.av[m];
            }
            __syncthreads();
            if (tid < MMD) {
                float sv = 0.f;
                for (int n = 0; n < NND; n++)
                    sv += s.w[n] * s.mem[n * 41 + tid];
                g_r[pout][b][tid] = sv;
            }
        }
        grid_barrier();
    }
}

extern "C" void kernel_launch(void* const* d_in, const int* in_sizes, int n_in,
                              void* d_out, int out_size) {
    (void)in_sizes; (void)n_in; (void)out_size;
    cudaFuncSetAttribute(ntm_kernel,
                         cudaFuncAttributeMaxDynamicSharedMemorySize,
                         (int)sizeof(Smem));
    ntm_kernel<<<NCTA, NTHR, sizeof(Smem)>>>(
        (const float*)d_in[0],  (const float*)d_in[1],  (const float*)d_in[2],
        (const float*)d_in[3],  (const float*)d_in[4],  (const float*)d_in[5],
        (const float*)d_in[6],  (const float*)d_in[7],  (const float*)d_in[8],
        (const float*)d_in[9],  (const float*)d_in[10], (const float*)d_in[11],
        (const float*)d_in[12], (const float*)d_in[13], (const float*)d_in[14],
        (const float*)d_in[15], (const float*)d_in[16], (const float*)d_in[17],
        (const float*)d_in[18], (float*)d_out);
}

// round 3
// speedup vs baseline: 1.2352x; 1.2352x over previous
#include <cuda_runtime.h>
#include <math.h>

#define BB 16
#define TT 1024
#define IND 64
#define OUTD 64
#define HHD 512
#define NND 128
#define MMD 40
#define KTOT 616      // IND + MMD + HHD
#define KPAD 628      // padded row stride (floats) = 157 float4
#define KP4  157
#define NCTA 128
#define NTHR 512
#define HPER 4        // h indices owned per CTA
#define EPSV 1e-8f
#define RCACHE 48     // projection rows cached in smem (of 121)

// ---------------- persistent global state ----------------
__device__ __align__(16) float g_h[2][BB][HHD];
__device__ __align__(16) float g_r[2][BB][MMD];
__device__ unsigned g_flags[NCTA * 32];   // one flag per CTA, 128B apart
__device__ unsigned g_epochg = 0;

static __device__ __forceinline__ unsigned ld_acq(const unsigned* p) {
    unsigned v;
    asm volatile("ld.acquire.gpu.global.u32 %0, [%1];" : "=r"(v) : "l"(p) : "memory");
    return v;
}
static __device__ __forceinline__ void st_rel(unsigned* p, unsigned v) {
    asm volatile("st.release.gpu.global.u32 [%0], %1;" :: "l"(p), "r"(v) : "memory");
}

// Flag-array grid barrier: parallel arrivals (own cache line each), one
// checker warp (CTA NCTA-1) scans flags and broadcasts via epoch.
// k is monotonically increasing; comparisons are wrap-safe.
static __device__ __forceinline__ void grid_barrier(int cta, unsigned k) {
    __syncthreads();
    const int tid = threadIdx.x;
    if (tid == 0) st_rel(&g_flags[cta * 32], k);
    if (cta == NCTA - 1 && tid < 32) {
        for (;;) {
            bool ok = true;
            #pragma unroll
            for (int q = 0; q < 4; q++) {
                unsigned v = ld_acq(&g_flags[(tid + 32 * q) * 32]);
                ok &= ((int)(v - k) >= 0);
            }
            if (__all_sync(0xffffffffu, ok)) break;
        }
        if (tid == 0) st_rel(&g_epochg, k);
    }
    if (tid == 0) {
        while ((int)(ld_acq(&g_epochg) - k) < 0) { }
    }
    __syncthreads();
}

struct __align__(16) Smem {
    // --- float4-accessed arrays first, all 16B-aligned offsets ---
    alignas(16) float W[16 * KPAD];     // this CTA's 16 gate rows [x|r|h]
    alignas(16) float inp[BB * KPAD];   // staged [x_t, r, h] per batch
    alignas(16) float red[8 * 64 * 4];  // split-K partials (reused in B)
    alignas(16) float pw[RCACHE * HHD]; // cached projection weight rows
    alignas(16) float mem[NND * 41];    // NTM memory (CTAs 0..15), padded
    // --- scalar-accessed tails ---
    float gate[16 * BB];
    float bias[16];
    float cst[64];          // cell-state slice
    float proj[NND];        // raw projection pre-activations (121 used)
    float key[MMD];
    float ev[MMD];
    float av[MMD];
    float z[NND];
    float wsm[NND];
    float rsc[16];
    float scal[4];          // [0]=||key||+eps, [1]=beta
    unsigned base_u;
};

static __device__ __forceinline__ const float* prow(int r,
    const float* W_k, const float* W_b, const float* W_e, const float* W_a)
{
    if (r < 40)  return W_k + r * HHD;
    if (r == 40) return W_b;
    if (r <= 80) return W_e + (r - 41) * HHD;
    return W_a + (r - 81) * HHD;
}

__global__ void __launch_bounds__(NTHR, 1) ntm_kernel(
    const float* __restrict__ x,    const float* __restrict__ h0,
    const float* __restrict__ c0,   const float* __restrict__ mem0,
    const float* __restrict__ r0_,  const float* __restrict__ W_ih,
    const float* __restrict__ b_ih, const float* __restrict__ W_hh,
    const float* __restrict__ b_hh, const float* __restrict__ W_fc,
    const float* __restrict__ b_fc, const float* __restrict__ W_e,
    const float* __restrict__ b_e,  const float* __restrict__ W_a,
    const float* __restrict__ b_a,  const float* __restrict__ W_k,
    const float* __restrict__ b_k,  const float* __restrict__ W_b,
    const float* __restrict__ b_b,  float* __restrict__ out)
{
    extern __shared__ unsigned char smem_raw[];
    Smem& s = *reinterpret_cast<Smem*>(smem_raw);
    const int cta = blockIdx.x;
    const int tid = threadIdx.x;
    const int j0 = cta * HPER;

    float* out_O = out;
    float* out_h = out + (size_t)BB * TT * OUTD;
    float* out_c = out_h + BB * HHD;

    if (tid == 0) s.base_u = ld_acq(&g_epochg);

    // ---------------- init: persistent weights & state ----------------
    for (int idx = tid; idx < 16 * KPAD; idx += NTHR) {
        int lrow = idx / KPAD, k = idx - lrow * KPAD;
        int gate = lrow >> 2, jl = lrow & 3;
        int gr = gate * HHD + j0 + jl;
        float v = 0.f;
        if (k < IND + MMD)      v = W_ih[gr * (IND + MMD) + k];
        else if (k < KTOT)      v = W_hh[gr * HHD + (k - (IND + MMD))];
        s.W[idx] = v;
    }
    if (tid < 16) {
        int gate = tid >> 2, jl = tid & 3;
        int gr = gate * HHD + j0 + jl;
        s.bias[tid] = b_ih[gr] + b_hh[gr];
    }
    if (tid < 64) {
        int b = tid >> 2, jl = tid & 3;
        g_h[0][b][j0 + jl] = h0[b * HHD + j0 + jl];
        s.cst[tid] = c0[b * HHD + j0 + jl];
    }
    if (cta == 0) {
        float* gr0 = &g_r[0][0][0];
        for (int i = tid; i < BB * MMD; i += NTHR) gr0[i] = r0_[i];
    }
    if (cta < BB) {
        for (int idx = tid; idx < NND * MMD; idx += NTHR) {
            int n = idx / MMD, m = idx - n * MMD;
            s.mem[n * 41 + m] = mem0[cta * NND * MMD + idx];
        }
        for (int idx = tid; idx < RCACHE * HHD; idx += NTHR) {
            int r = idx >> 9, k = idx & (HHD - 1);
            s.pw[idx] = prow(r, W_k, W_b, W_e, W_a)[k];
        }
    }
    __syncthreads();
    unsigned barc = s.base_u;
    grid_barrier(cta, ++barc);

    const int kc = tid >> 6;          // split-K chunk 0..7
    const int tile = tid & 63;
    const int rp = tile & 7;
    const int bp = tile >> 3;
    const int wrp = tid >> 5, lane = tid & 31;

    for (int t = 0; t < TT; t++) {
        const int pin = t & 1, pout = pin ^ 1;

        // ========== Phase A: gates GEMM + LSTM pointwise ==========
        for (int idx = tid; idx < BB * KPAD; idx += NTHR) {
            int b = idx / KPAD, k = idx - b * KPAD;
            float v = 0.f;
            if (k < IND)            v = x[(b * TT + t) * IND + k];
            else if (k < IND + MMD) v = __ldcg(&g_r[pin][b][k - IND]);
            else if (k < KTOT)      v = __ldcg(&g_h[pin][b][k - (IND + MMD)]);
            s.inp[idx] = v;
        }
        __syncthreads();
        {
            const float4* W4 = reinterpret_cast<const float4*>(s.W);
            const float4* I4 = reinterpret_cast<const float4*>(s.inp);
            const int koff = kc * 20;
            const float4* w0p = W4 + (2 * rp) * KP4 + koff;
            const float4* w1p = w0p + KP4;
            const float4* i0p = I4 + (2 * bp) * KP4 + koff;
            const float4* i1p = i0p + KP4;
            float a00 = 0.f, a01 = 0.f, a10 = 0.f, a11 = 0.f;
            if (kc < 7) {
                #pragma unroll
                for (int q = 0; q < 20; q++) {
                    float4 wa = w0p[q], wb = w1p[q], ia = i0p[q], ib = i1p[q];
                    a00 += wa.x*ia.x; a00 += wa.y*ia.y; a00 += wa.z*ia.z; a00 += wa.w*ia.w;
                    a01 += wa.x*ib.x; a01 += wa.y*ib.y; a01 += wa.z*ib.z; a01 += wa.w*ib.w;
                    a10 += wb.x*ia.x; a10 += wb.y*ia.y; a10 += wb.z*ia.z; a10 += wb.w*ia.w;
                    a11 += wb.x*ib.x; a11 += wb.y*ib.y; a11 += wb.z*ib.z; a11 += wb.w*ib.w;
                }
            } else {
                #pragma unroll
                for (int q = 0; q < 17; q++) {
                    float4 wa = w0p[q], wb = w1p[q], ia = i0p[q], ib = i1p[q];
                    a00 += wa.x*ia.x; a00 += wa.y*ia.y; a00 += wa.z*ia.z; a00 += wa.w*ia.w;
                    a01 += wa.x*ib.x; a01 += wa.y*ib.y; a01 += wa.z*ib.z; a01 += wa.w*ib.w;
                    a10 += wb.x*ia.x; a10 += wb.y*ia.y; a10 += wb.z*ia.z; a10 += wb.w*ia.w;
                    a11 += wb.x*ib.x; a11 += wb.y*ib.y; a11 += wb.z*ib.z; a11 += wb.w*ib.w;
                }
            }
            float* rb = &s.red[(kc * 64 + tile) * 4];
            rb[0] = a00; rb[1] = a01; rb[2] = a10; rb[3] = a11;
        }
        __syncthreads();
        if (tid < 256) {
            int lrow = tid & 15, b = tid >> 4;
            int tl = (b >> 1) * 8 + (lrow >> 1);
            int j = (lrow & 1) * 2 + (b & 1);
            float v = s.bias[lrow];
            #pragma unroll
            for (int c2 = 0; c2 < 8; c2++) v += s.red[(c2 * 64 + tl) * 4 + j];
            s.gate[lrow * BB + b] = v;
        }
        __syncthreads();
        if (tid < 64) {
            int b = tid >> 2, jl = tid & 3;
            float gi = s.gate[(0 * 4 + jl) * BB + b];
            float gf = s.gate[(1 * 4 + jl) * BB + b];
            float gg = s.gate[(2 * 4 + jl) * BB + b];
            float go = s.gate[(3 * 4 + jl) * BB + b];
            float iv = 1.f / (1.f + expf(-gi));
            float fv = 1.f / (1.f + expf(-gf));
            float gv = tanhf(gg);
            float ov = 1.f / (1.f + expf(-go));
            float cn = fv * s.cst[tid] + iv * gv;
            float hn = ov * tanhf(cn);
            s.cst[tid] = cn;
            g_h[pout][b][j0 + jl] = hn;
            if (t == TT - 1) {
                out_h[b * HHD + j0 + jl] = hn;
                out_c[b * HHD + j0 + jl] = cn;
            }
        }
        grid_barrier(cta, ++barc);

        // ========== Phase B ==========
        if (cta < BB) {
            const int b = cta;
            // --- projections key/beta/e/a: 121 rows x 512 GEMV ---
            {
                const float4* h4 = reinterpret_cast<const float4*>(&g_h[pout][b][0]);
                float4 hv0 = __ldcg(h4 + lane);
                float4 hv1 = __ldcg(h4 + lane + 32);
                float4 hv2 = __ldcg(h4 + lane + 64);
                float4 hv3 = __ldcg(h4 + lane + 96);
                #pragma unroll
                for (int jr = 0; jr < 8; jr++) {
                    int r = wrp + 16 * jr;
                    if (r <= 120) {                       // warp-uniform
                        float4 a0, a1, a2, a3;
                        if (r < RCACHE) {
                            const float4* w4 = reinterpret_cast<const float4*>(&s.pw[r * HHD]);
                            a0 = w4[lane]; a1 = w4[lane + 32];
                            a2 = w4[lane + 64]; a3 = w4[lane + 96];
                        } else {
                            const float4* w4 = reinterpret_cast<const float4*>(
                                prow(r, W_k, W_b, W_e, W_a));
                            a0 = __ldg(w4 + lane); a1 = __ldg(w4 + lane + 32);
                            a2 = __ldg(w4 + lane + 64); a3 = __ldg(w4 + lane + 96);
                        }
                        float acc = 0.f;
                        acc += a0.x*hv0.x; acc += a0.y*hv0.y; acc += a0.z*hv0.z; acc += a0.w*hv0.w;
                        acc += a1.x*hv1.x; acc += a1.y*hv1.y; acc += a1.z*hv1.z; acc += a1.w*hv1.w;
                        acc += a2.x*hv2.x; acc += a2.y*hv2.y; acc += a2.z*hv2.z; acc += a2.w*hv2.w;
                        acc += a3.x*hv3.x; acc += a3.y*hv3.y; acc += a3.z*hv3.z; acc += a3.w*hv3.w;
                        #pragma unroll
                        for (int off = 16; off; off >>= 1)
                            acc += __shfl_xor_sync(0xffffffffu, acc, off);
                        if (lane == 0) s.proj[r] = acc;
                    }
                }
            }
            __syncthreads();
            if (tid < 121) {
                float v = s.proj[tid];
                if (tid < 40) {
                    s.key[tid] = tanhf(v + b_k[tid]);
                } else if (tid == 40) {
                    float zz = v + b_b[0];
                    s.scal[1] = fmaxf(zz, 0.f) + log1pf(expf(-fabsf(zz))) + EPSV;
                } else if (tid <= 80) {
                    int m = tid - 41;
                    s.ev[m] = 1.f / (1.f + expf(-(v + b_e[m])));
                } else {
                    int m = tid - 81;
                    s.av[m] = tanhf(v + b_a[m]);
                }
            }
            __syncthreads();
            // --- key norm ---
            if (tid < 32) {
                float v = 0.f;
                if (tid < MMD)      { float kv = s.key[tid];      v  = kv * kv; }
                if (tid + 32 < MMD) { float kv = s.key[tid + 32]; v += kv * kv; }
                #pragma unroll
                for (int off = 16; off; off >>= 1)
                    v += __shfl_xor_sync(0xffffffffu, v, off);
                if (tid == 0) s.scal[0] = sqrtf(v) + EPSV;
            }
            __syncthreads();
            // --- cosine sim * beta ---
            if (tid < NND) {
                const float* mr = &s.mem[tid * 41];
                float dot = 0.f, nrm = 0.f;
                #pragma unroll
                for (int m = 0; m < MMD; m++) {
                    float mv = mr[m];
                    dot += mv * s.key[m];
                    nrm += mv * mv;
                }
                float sim = dot / ((sqrtf(nrm) + EPSV) * s.scal[0]);
                s.z[tid] = s.scal[1] * sim;
            }
            __syncthreads();
            float zl = (tid < NND) ? s.z[tid] : 0.f;
            if (tid < NND) {
                float mv = zl;
                #pragma unroll
                for (int off = 16; off; off >>= 1)
                    mv = fmaxf(mv, __shfl_xor_sync(0xffffffffu, mv, off));
                if ((tid & 31) == 0) s.rsc[tid >> 5] = mv;
            }
            __syncthreads();
            if (tid < NND) {
                float gmax = fmaxf(fmaxf(s.rsc[0], s.rsc[1]),
                                   fmaxf(s.rsc[2], s.rsc[3]));
                float ee = expf(zl - gmax);
                s.wsm[tid] = ee;
                float sv = ee;
                #pragma unroll
                for (int off = 16; off; off >>= 1)
                    sv += __shfl_xor_sync(0xffffffffu, sv, off);
                if ((tid & 31) == 0) s.rsc[4 + (tid >> 5)] = sv;
            }
            __syncthreads();
            if (tid < NND) {
                float tot = s.rsc[4] + s.rsc[5] + s.rsc[6] + s.rsc[7];
                float wv = s.wsm[tid] / tot;
                s.wsm[tid] = wv;
                float* mr = &s.mem[tid * 41];
                #pragma unroll
                for (int m = 0; m < MMD; m++)
                    mr[m] = mr[m] * (1.f - wv * s.ev[m]) + wv * s.av[m];
            }
            __syncthreads();
            // --- read: r = w^T M (parallel partials, reuse s.red) ---
            if (tid < 320) {
                int m = tid >> 3, p = tid & 7;
                float sv = 0.f;
                #pragma unroll
                for (int n = p * 16; n < p * 16 + 16; n++)
                    sv += s.wsm[n] * s.mem[n * 41 + m];
                s.red[tid] = sv;
            }
            __syncthreads();
            if (tid < MMD) {
                float sv = 0.f;
                #pragma unroll
                for (int p = 0; p < 8; p++) sv += s.red[tid * 8 + p];
                g_r[pout][b][tid] = sv;
            }
        } else {
            // --- fc output rows (no downstream dependency) ---
            int gid = tid >> 4, l16 = tid & 15;
            int d = (cta - 16) + 112 * gid;
            bool valid = (d < 1024);
            int d2 = valid ? d : 0;
            int b = d2 >> 6, row = d2 & 63;
            const float4* w4 = reinterpret_cast<const float4*>(W_fc + row * HHD);
            const float4* h4 = reinterpret_cast<const float4*>(&g_h[pout][b][0]);
            float acc = 0.f;
            #pragma unroll
            for (int q = 0; q < 8; q++) {
                float4 wv = __ldg(w4 + l16 + 16 * q);
                float4 hv = __ldcg(h4 + l16 + 16 * q);
                acc += wv.x*hv.x; acc += wv.y*hv.y; acc += wv.z*hv.z; acc += wv.w*hv.w;
            }
            #pragma unroll
            for (int off = 8; off; off >>= 1)
                acc += __shfl_xor_sync(0xffffffffu, acc, off);
            if (valid && l16 == 0)
                out_O[(b * TT + t) * OUTD + row] = tanhf(acc + b_fc[row]);
        }
        grid_barrier(cta, ++barc);
    }
}

extern "C" void kernel_launch(void* const* d_in, const int* in_sizes, int n_in,
                              void* d_out, int out_size) {
    (void)in_sizes; (void)n_in; (void)out_size;
    cudaFuncSetAttribute(ntm_kernel,
                         cudaFuncAttributeMaxDynamicSharedMemorySize,
                         (int)sizeof(Smem));
    ntm_kernel<<<NCTA, NTHR, sizeof(Smem)>>>(
        (const float*)d_in[0],  (const float*)d_in[1],  (const float*)d_in[2],
        (const float*)d_in[3],  (const float*)d_in[4],  (const float*)d_in[5],
        (const float*)d_in[6],  (const float*)d_in[7],  (const float*)d_in[8],
        (const float*)d_in[9],  (const float*)d_in[10], (const float*)d_in[11],
        (const float*)d_in[12], (const float*)d_in[13], (const float*)d_in[14],
        (const float*)d_in[15], (const float*)d_in[16], (const float*)d_in[17],
        (const float*)d_in[18], (float*)d_out);
}

// round 5
// speedup vs baseline: 1.3728x; 1.1114x over previous
#include <cuda_runtime.h>
#include <math.h>

#define BB 16
#define TT 1024
#define IND 64
#define OUTD 64
#define HHD 512
#define NND 128
#define MMD 40
#define KTOT 616      // IND + MMD + HHD
#define KPAD 628      // padded row stride (floats) = 157 float4
#define KP4  157
#define NCTA 128
#define NTHR 512
#define HPER 4
#define EPSV 1e-8f
#define RCACHE 41     // W_k rows + W_b cached in smem

// ---------------- persistent global state ----------------
__device__ __align__(16) float g_h[2][BB][HHD];
__device__ __align__(16) float g_r[2][BB][MMD];
__device__ unsigned g_flags[NCTA * 32];   // one flag per CTA, 128B apart

static __device__ __forceinline__ unsigned ld_acq(const unsigned* p) {
    unsigned v;
    asm volatile("ld.acquire.gpu.global.u32 %0, [%1];" : "=r"(v) : "l"(p) : "memory");
    return v;
}
static __device__ __forceinline__ void st_rel(unsigned* p, unsigned v) {
    asm volatile("st.release.gpu.global.u32 [%0], %1;" :: "l"(p), "r"(v) : "memory");
}

// All-poll grid barrier: each CTA's warp0 reads all 128 flags (4/lane).
// Detection latency = last arrival + one L2 round trip.
static __device__ __forceinline__ void grid_barrier(int cta, unsigned k) {
    __syncthreads();
    if (threadIdx.x < 32) {
        if (threadIdx.x == 0) st_rel(&g_flags[cta * 32], k);
        for (;;) {
            bool ok = true;
            #pragma unroll
            for (int q = 0; q < 4; q++) {
                unsigned v = ld_acq(&g_flags[(threadIdx.x + 32 * q) * 32]);
                ok &= ((int)(v - k) >= 0);
            }
            if (__all_sync(0xffffffffu, ok)) break;
        }
    }
    __syncthreads();
}

struct __align__(16) Smem {
    alignas(16) float W[16 * KPAD];      // 40.2 KB  gate-weight slice
    alignas(16) float inp[BB * KPAD];    // 40.2 KB  staged [x|r|h]
    alignas(16) float red[32 * 16 * 16]; // 32 KB    split-K partials
    alignas(16) float pw[RCACHE * HHD];  // 84 KB    W_k + W_b rows
    alignas(16) float mem[NND * 41];     // 21 KB    NTM memory (CTAs 0..15)
    float gate[16 * BB];
    float bias[16];
    float cst[64];
    float proj[NND];
    float key[MMD];
    float ev[MMD];
    float av[MMD];
    float z[NND];         // dot/(||m||+eps) per slot
    float wsm[NND];
    float scal[4];        // [0]=||key||+eps, [1]=beta
    unsigned base_u;
};

static __device__ __forceinline__ const float* prow(int r,
    const float* W_k, const float* W_b, const float* W_e, const float* W_a)
{
    if (r < 40)  return W_k + r * HHD;
    if (r == 40) return W_b;
    if (r <= 80) return W_e + (r - 41) * HHD;
    return W_a + (r - 81) * HHD;
}

#define DOT4(acc, wv, iv) \
    acc += wv.x*iv.x; acc += wv.y*iv.y; acc += wv.z*iv.z; acc += wv.w*iv.w;

__global__ void __launch_bounds__(NTHR, 1) ntm_kernel(
    const float* __restrict__ x,    const float* __restrict__ h0,
    const float* __restrict__ c0,   const float* __restrict__ mem0,
    const float* __restrict__ r0_,  const float* __restrict__ W_ih,
    const float* __restrict__ b_ih, const float* __restrict__ W_hh,
    const float* __restrict__ b_hh, const float* __restrict__ W_fc,
    const float* __restrict__ b_fc, const float* __restrict__ W_e,
    const float* __restrict__ b_e,  const float* __restrict__ W_a,
    const float* __restrict__ b_a,  const float* __restrict__ W_k,
    const float* __restrict__ b_k,  const float* __restrict__ W_b,
    const float* __restrict__ b_b,  float* __restrict__ out)
{
    extern __shared__ unsigned char smem_raw[];
    Smem& s = *reinterpret_cast<Smem*>(smem_raw);
    const int cta = blockIdx.x;
    const int tid = threadIdx.x;
    const int j0 = cta * HPER;

    float* out_O = out;
    float* out_h = out + (size_t)BB * TT * OUTD;
    float* out_c = out_h + BB * HHD;

    if (tid == 0) s.base_u = ld_acq(&g_flags[cta * 32]);

    // ---------------- init ----------------
    for (int idx = tid; idx < 16 * KPAD; idx += NTHR) {
        int lrow = idx / KPAD, k = idx - lrow * KPAD;
        int gate = lrow >> 2, jl = lrow & 3;
        int gr = gate * HHD + j0 + jl;
        float v = 0.f;
        if (k < IND + MMD)      v = W_ih[gr * (IND + MMD) + k];
        else if (k < KTOT)      v = W_hh[gr * HHD + (k - (IND + MMD))];
        s.W[idx] = v;
    }
    // stage step-0 input: x[0], h0, zeros in padding (r-part filled in Phase A)
    for (int idx = tid; idx < BB * KPAD; idx += NTHR) {
        int b = idx / KPAD, k = idx - b * KPAD;
        float v = 0.f;
        if (k < IND)                       v = x[(b * TT) * IND + k];
        else if (k >= IND + MMD && k < KTOT) v = h0[b * HHD + k - (IND + MMD)];
        s.inp[idx] = v;
    }
    if (tid < 16) {
        int gate = tid >> 2, jl = tid & 3;
        int gr = gate * HHD + j0 + jl;
        s.bias[tid] = b_ih[gr] + b_hh[gr];
    }
    if (tid < 64) {
        int b = tid >> 2, jl = tid & 3;
        g_h[0][b][j0 + jl] = h0[b * HHD + j0 + jl];
        s.cst[tid] = c0[b * HHD + j0 + jl];
    }
    if (cta == 0) {
        float* gr0 = &g_r[0][0][0];
        for (int i = tid; i < BB * MMD; i += NTHR) gr0[i] = r0_[i];
    }
    if (cta < BB) {
        for (int idx = tid; idx < NND * MMD; idx += NTHR) {
            int n = idx / MMD, m = idx - n * MMD;
            s.mem[n * 41 + m] = mem0[cta * NND * MMD + idx];
        }
        for (int idx = tid; idx < RCACHE * HHD; idx += NTHR) {
            int r = idx >> 9, k = idx & (HHD - 1);
            s.pw[idx] = prow(r, W_k, W_b, W_e, W_a)[k];
        }
    }
    __syncthreads();
    unsigned barc = s.base_u;
    grid_barrier(cta, ++barc);

    // GEMM thread mapping: 32 split-K chunks x 16 (4x4) tiles
    const int kc = tid >> 4;               // 0..31
    const int tile = tid & 15;
    const int rq = tile & 3;               // row quad
    const int bq = tile >> 2;              // batch quad
    const int koff = (kc < 29) ? kc * 5 : 145 + (kc - 29) * 4;
    const int wrp = tid >> 5, lane = tid & 31;

    for (int t = 0; t < TT; t++) {
        const int pin = t & 1, pout = pin ^ 1;

        // ========== Phase A ==========
        // fill only the r-slice (rest prestaged during previous Phase B)
        for (int idx = tid; idx < BB * MMD; idx += NTHR) {
            int b = idx / MMD, m = idx - b * MMD;
            s.inp[b * KPAD + IND + m] = __ldcg(&g_r[pin][b][m]);
        }
        __syncthreads();
        {
            const float4* W4 = reinterpret_cast<const float4*>(s.W);
            const float4* I4 = reinterpret_cast<const float4*>(s.inp);
            const float4* w0 = W4 + (4 * rq + 0) * KP4 + koff;
            const float4* w1 = w0 + KP4;
            const float4* w2 = w1 + KP4;
            const float4* w3 = w2 + KP4;
            const float4* i0 = I4 + (4 * bq + 0) * KP4 + koff;
            const float4* i1 = i0 + KP4;
            const float4* i2 = i1 + KP4;
            const float4* i3 = i2 + KP4;
            float a[16];
            #pragma unroll
            for (int q = 0; q < 16; q++) a[q] = 0.f;
            const int klen = (kc < 29) ? 5 : 4;
            #pragma unroll 5
            for (int q = 0; q < klen; q++) {
                float4 wv0 = w0[q], wv1 = w1[q], wv2 = w2[q], wv3 = w3[q];
                float4 iv0 = i0[q], iv1 = i1[q], iv2 = i2[q], iv3 = i3[q];
                DOT4(a[0],  wv0, iv0) DOT4(a[1],  wv0, iv1)
                DOT4(a[2],  wv0, iv2) DOT4(a[3],  wv0, iv3)
                DOT4(a[4],  wv1, iv0) DOT4(a[5],  wv1, iv1)
                DOT4(a[6],  wv1, iv2) DOT4(a[7],  wv1, iv3)
                DOT4(a[8],  wv2, iv0) DOT4(a[9],  wv2, iv1)
                DOT4(a[10], wv2, iv2) DOT4(a[11], wv2, iv3)
                DOT4(a[12], wv3, iv0) DOT4(a[13], wv3, iv1)
                DOT4(a[14], wv3, iv2) DOT4(a[15], wv3, iv3)
            }
            float4* red4 = reinterpret_cast<float4*>(s.red);
            const int rbase = (kc * 16 + tile) * 4;
            red4[rbase + 0] = make_float4(a[0],  a[1],  a[2],  a[3]);
            red4[rbase + 1] = make_float4(a[4],  a[5],  a[6],  a[7]);
            red4[rbase + 2] = make_float4(a[8],  a[9],  a[10], a[11]);
            red4[rbase + 3] = make_float4(a[12], a[13], a[14], a[15]);
        }
        __syncthreads();
        if (tid < 256) {
            int lrow = tid & 15, b = tid >> 4;
            int tl = (b >> 2) * 4 + (lrow >> 2);       // bq*4 + rq
            int j = (lrow & 3) * 4 + (b & 3);          // jr*4 + jb
            float v = s.bias[lrow];
            #pragma unroll
            for (int c2 = 0; c2 < 32; c2++) v += s.red[(c2 * 16 + tl) * 16 + j];
            s.gate[lrow * BB + b] = v;
        }
        __syncthreads();
        if (tid < 64) {
            int b = tid >> 2, jl = tid & 3;
            float gi = s.gate[(0 * 4 + jl) * BB + b];
            float gf = s.gate[(1 * 4 + jl) * BB + b];
            float gg = s.gate[(2 * 4 + jl) * BB + b];
            float go = s.gate[(3 * 4 + jl) * BB + b];
            float iv = 1.f / (1.f + expf(-gi));
            float fv = 1.f / (1.f + expf(-gf));
            float gv = tanhf(gg);
            float ov = 1.f / (1.f + expf(-go));
            float cn = fv * s.cst[tid] + iv * gv;
            float hn = ov * tanhf(cn);
            s.cst[tid] = cn;
            g_h[pout][b][j0 + jl] = hn;
            if (t == TT - 1) {
                out_h[b * HHD + j0 + jl] = hn;
                out_c[b * HHD + j0 + jl] = cn;
            }
        }
        grid_barrier(cta, ++barc);

        // ========== Phase B ==========
        if (cta < BB) {
            const int b = cta;
            // --- 121-row projection GEMV over h ---
            {
                const float4* h4 = reinterpret_cast<const float4*>(&g_h[pout][b][0]);
                float4 hv0 = __ldcg(h4 + lane);
                float4 hv1 = __ldcg(h4 + lane + 32);
                float4 hv2 = __ldcg(h4 + lane + 64);
                float4 hv3 = __ldcg(h4 + lane + 96);
                #pragma unroll
                for (int jr = 0; jr < 8; jr++) {
                    int r = wrp + 16 * jr;
                    if (r <= 120) {
                        float4 a0, a1, a2, a3;
                        if (r < RCACHE) {
                            const float4* w4 = reinterpret_cast<const float4*>(&s.pw[r * HHD]);
                            a0 = w4[lane];      a1 = w4[lane + 32];
                            a2 = w4[lane + 64]; a3 = w4[lane + 96];
                        } else {
                            const float4* w4 = reinterpret_cast<const float4*>(
                                prow(r, W_k, W_b, W_e, W_a));
                            a0 = __ldg(w4 + lane);      a1 = __ldg(w4 + lane + 32);
                            a2 = __ldg(w4 + lane + 64); a3 = __ldg(w4 + lane + 96);
                        }
                        float acc = 0.f;
                        DOT4(acc, a0, hv0) DOT4(acc, a1, hv1)
                        DOT4(acc, a2, hv2) DOT4(acc, a3, hv3)
                        #pragma unroll
                        for (int off = 16; off; off >>= 1)
                            acc += __shfl_xor_sync(0xffffffffu, acc, off);
                        if (lane == 0) s.proj[r] = acc;
                    }
                }
            }
            __syncthreads();
            if (tid < 121) {
                float v = s.proj[tid];
                if (tid < 40) {
                    s.key[tid] = tanhf(v + b_k[tid]);
                } else if (tid == 40) {
                    float zz = v + b_b[0];
                    s.scal[1] = fmaxf(zz, 0.f) + log1pf(expf(-fabsf(zz))) + EPSV;
                } else if (tid <= 80) {
                    int m = tid - 41;
                    s.ev[m] = 1.f / (1.f + expf(-(v + b_e[m])));
                } else {
                    int m = tid - 81;
                    s.av[m] = tanhf(v + b_a[m]);
                }
            }
            __syncthreads();
            // --- z[n] = dot(mem_n,key)/(||mem_n||+eps); warp 8 does ||key|| ---
            if (tid < NND) {
                const float* mr = &s.mem[tid * 41];
                float dot = 0.f, nrm = 0.f;
                #pragma unroll
                for (int m = 0; m < MMD; m++) {
                    float mv = mr[m];
                    dot += mv * s.key[m];
                    nrm += mv * mv;
                }
                s.z[tid] = dot / (sqrtf(nrm) + EPSV);
            } else if (wrp == 8) {
                float v = 0.f;
                if (lane < MMD)      { float kv = s.key[lane];      v  = kv * kv; }
                if (lane + 32 < MMD) { float kv = s.key[lane + 32]; v += kv * kv; }
                #pragma unroll
                for (int off = 16; off; off >>= 1)
                    v += __shfl_xor_sync(0xffffffffu, v, off);
                if (lane == 0) s.scal[0] = sqrtf(v) + EPSV;
            }
            __syncthreads();
            // --- softmax over 128 entries, warp 0 only (4/lane) ---
            if (wrp == 0) {
                float bscale = s.scal[1] / s.scal[0];
                float z0 = s.z[lane]       * bscale;
                float z1 = s.z[lane + 32]  * bscale;
                float z2 = s.z[lane + 64]  * bscale;
                float z3 = s.z[lane + 96]  * bscale;
                float mx = fmaxf(fmaxf(z0, z1), fmaxf(z2, z3));
                #pragma unroll
                for (int off = 16; off; off >>= 1)
                    mx = fmaxf(mx, __shfl_xor_sync(0xffffffffu, mx, off));
                float e0 = expf(z0 - mx), e1 = expf(z1 - mx);
                float e2 = expf(z2 - mx), e3 = expf(z3 - mx);
                float sv = e0 + e1 + e2 + e3;
                #pragma unroll
                for (int off = 16; off; off >>= 1)
                    sv += __shfl_xor_sync(0xffffffffu, sv, off);
                float inv = 1.f / sv;
                s.wsm[lane]      = e0 * inv;
                s.wsm[lane + 32] = e1 * inv;
                s.wsm[lane + 64] = e2 * inv;
                s.wsm[lane + 96] = e3 * inv;
            }
            __syncthreads();
            // --- memory erase/add ---
            if (tid < NND) {
                float wv = s.wsm[tid];
                float* mr = &s.mem[tid * 41];
                #pragma unroll
                for (int m = 0; m < MMD; m++)
                    mr[m] = mr[m] * (1.f - wv * s.ev[m]) + wv * s.av[m];
            }
            __syncthreads();
            // --- read r = w^T M ---
            if (tid < 320) {
                int m = tid >> 3, p = tid & 7;
                float sv = 0.f;
                #pragma unroll
                for (int n = p * 16; n < p * 16 + 16; n++)
                    sv += s.wsm[n] * s.mem[n * 41 + m];
                s.red[tid] = sv;
            }
            __syncthreads();
            if (tid < MMD) {
                float sv = 0.f;
                #pragma unroll
                for (int p = 0; p < 8; p++) sv += s.red[tid * 8 + p];
                g_r[pout][b][tid] = sv;
            }
        } else {
            // --- fc rows ---
            int gid = tid >> 4, l16 = tid & 15;
            int d = (cta - 16) + 112 * gid;
            bool valid = (d < 1024);
            int d2 = valid ? d : 0;
            int b = d2 >> 6, row = d2 & 63;
            const float4* w4 = reinterpret_cast<const float4*>(W_fc + row * HHD);
            const float4* h4 = reinterpret_cast<const float4*>(&g_h[pout][b][0]);
            float acc = 0.f;
            #pragma unroll
            for (int q = 0; q < 8; q++) {
                float4 wv = __ldg(w4 + l16 + 16 * q);
                float4 hv = __ldcg(h4 + l16 + 16 * q);
                DOT4(acc, wv, hv)
            }
            #pragma unroll
            for (int off = 8; off; off >>= 1)
                acc += __shfl_xor_sync(0xffffffffu, acc, off);
            if (valid && l16 == 0)
                out_O[(b * TT + t) * OUTD + row] = tanhf(acc + b_fc[row]);
        }
        // --- prestage x(t+1) and h(pout) for next step (all CTAs) ---
        for (int idx = tid; idx < BB * KPAD; idx += NTHR) {
            int b = idx / KPAD, k = idx - b * KPAD;
            if (k < IND) {
                s.inp[idx] = (t + 1 < TT) ? x[(b * TT + t + 1) * IND + k] : 0.f;
            } else if (k >= IND + MMD && k < KTOT) {
                s.inp[idx] = __ldcg(&g_h[pout][b][k - (IND + MMD)]);
            } else if (k >= KTOT) {
                s.inp[idx] = 0.f;
            }
        }
        grid_barrier(cta, ++barc);
    }
}

extern "C" void kernel_launch(void* const* d_in, const int* in_sizes, int n_in,
                              void* d_out, int out_size) {
    (void)in_sizes; (void)n_in; (void)out_size;
    cudaFuncSetAttribute(ntm_kernel,
                         cudaFuncAttributeMaxDynamicSharedMemorySize,
                         (int)sizeof(Smem));
    ntm_kernel<<<NCTA, NTHR, sizeof(Smem)>>>(
        (const float*)d_in[0],  (const float*)d_in[1],  (const float*)d_in[2],
        (const float*)d_in[3],  (const float*)d_in[4],  (const float*)d_in[5],
        (const float*)d_in[6],  (const float*)d_in[7],  (const float*)d_in[8],
        (const float*)d_in[9],  (const float*)d_in[10], (const float*)d_in[11],
        (const float*)d_in[12], (const float*)d_in[13], (const float*)d_in[14],
        (const float*)d_in[15], (const float*)d_in[16], (const float*)d_in[17],
        (const float*)d_in[18], (float*)d_out);
}

// round 6
// speedup vs baseline: 2.1304x; 1.5519x over previous
#include <cuda_runtime.h>
#include <math.h>

#define BB 16
#define TT 1024
#define IND 64
#define OUTD 64
#define HHD 512
#define NND 128
#define MMD 40
#define KTOT 616        // IND + HHD + MMD, order [x|h|r]
#define KP4  157        // padded row stride in float4 (157*4=628 floats)
#define KPAD 628
#define NCTA 128
#define NMEM 16
#define NGEMM 112
#define NTHR 512
#define RWS 20          // gate rows per gemm CTA (4 gates x up-to-5 h-idx)
#define EPSV 1e-8f
#define RCACHE 80       // projection rows cached in smem (of 121)

// ---------------- persistent global state ----------------
__device__ __align__(16) float g_h[2][BB][HHD];
__device__ __align__(16) float g_r[2][BB][MMD];
__device__ unsigned g_flags[NCTA * 32];    // barrier flags, 128B apart
__device__ unsigned g_rflags[NMEM * 32];   // r-ready flags

static __device__ __forceinline__ unsigned ld_acq(const unsigned* p) {
    unsigned v;
    asm volatile("ld.acquire.gpu.global.u32 %0, [%1];" : "=r"(v) : "l"(p) : "memory");
    return v;
}
static __device__ __forceinline__ void st_rel(unsigned* p, unsigned v) {
    asm volatile("st.release.gpu.global.u32 [%0], %1;" :: "l"(p), "r"(v) : "memory");
}

// All-poll grid barrier: each CTA's warp0 reads all 128 flags (4/lane).
static __device__ __forceinline__ void grid_barrier(int cta, unsigned k) {
    __syncthreads();
    if (threadIdx.x < 32) {
        if (threadIdx.x == 0) {
            __threadfence();
            st_rel(&g_flags[cta * 32], k);
        }
        for (;;) {
            bool ok = true;
            #pragma unroll
            for (int q = 0; q < 4; q++) {
                unsigned v = ld_acq(&g_flags[(threadIdx.x + 32 * q) * 32]);
                ok &= ((int)(v - k) >= 0);
            }
            if (__all_sync(0xffffffffu, ok)) break;
        }
    }
    __syncthreads();
}

struct __align__(16) GemmS {
    alignas(16) float W[RWS * KPAD];       // 50.2 KB  gate-weight slice [x|h|r]
    alignas(16) float inp[BB * KPAD];      // 40.2 KB  staged [x|h|r]
    alignas(16) float red[32 * 16 * RWS];  // 41 KB    split-K partials
    float gate[RWS * BB];
    float bias[RWS];
    float cst[5 * BB];
};
struct __align__(16) MemS {
    alignas(16) float pw[RCACHE * HHD];    // 163.8 KB projection weight rows
    float mem[NND * 41];                   // 21 KB
    float rred[320];
    float proj[NND];
    float key[MMD];
    float ev[MMD];
    float av[MMD];
    float z[NND];
    float wsm[NND];
    float scal[4];                         // [0]=||key||+eps, [1]=beta
};
struct __align__(16) Smem {
    union { GemmS g; MemS m; } u;
    unsigned base_u;
    unsigned rbase_u;
};

static __device__ __forceinline__ const float* prow(int r,
    const float* W_k, const float* W_b, const float* W_e, const float* W_a)
{
    if (r < 40)  return W_k + r * HHD;
    if (r == 40) return W_b;
    if (r <= 80) return W_e + (r - 41) * HHD;
    return W_a + (r - 81) * HHD;
}

#define DOT4(acc, wv, iv) \
    acc += wv.x*iv.x; acc += wv.y*iv.y; acc += wv.z*iv.z; acc += wv.w*iv.w;

// xh-part GEMM (576 dims = f4 0..143), conflict-free interleaved mapping:
// thread rows rg+4i, batches bg+4j.
static __device__ __forceinline__ void gemm_xh(GemmS& G, int tid) {
    const int kc = tid >> 4, tile = tid & 15;
    const int rg = tile & 3, bg = tile >> 2;
    const int koff = (kc < 16) ? kc * 5 : 80 + (kc - 16) * 4;
    const int klen = (kc < 16) ? 5 : 4;
    const float4* W4 = reinterpret_cast<const float4*>(G.W);
    const float4* I4 = reinterpret_cast<const float4*>(G.inp);
    float a[20];
    #pragma unroll
    for (int q = 0; q < 20; q++) a[q] = 0.f;
    #pragma unroll 5
    for (int q = 0; q < klen; q++) {
        float4 wv[5], iv[4];
        #pragma unroll
        for (int i = 0; i < 5; i++) wv[i] = W4[(rg + 4 * i) * KP4 + koff + q];
        #pragma unroll
        for (int j = 0; j < 4; j++) iv[j] = I4[(bg + 4 * j) * KP4 + koff + q];
        #pragma unroll
        for (int i = 0; i < 5; i++) {
            #pragma unroll
            for (int j = 0; j < 4; j++) { DOT4(a[i * 4 + j], wv[i], iv[j]) }
        }
    }
    float* rb = &G.red[(kc * 16 + tile) * RWS];
    #pragma unroll
    for (int q = 0; q < 20; q++) rb[q] = a[q];
}

__global__ void __launch_bounds__(NTHR, 1) ntm_kernel(
    const float* __restrict__ x,    const float* __restrict__ h0,
    const float* __restrict__ c0,   const float* __restrict__ mem0,
    const float* __restrict__ r0_,  const float* __restrict__ W_ih,
    const float* __restrict__ b_ih, const float* __restrict__ W_hh,
    const float* __restrict__ b_hh, const float* __restrict__ W_fc,
    const float* __restrict__ b_fc, const float* __restrict__ W_e,
    const float* __restrict__ b_e,  const float* __restrict__ W_a,
    const float* __restrict__ b_a,  const float* __restrict__ W_k,
    const float* __restrict__ b_k,  const float* __restrict__ W_b,
    const float* __restrict__ b_b,  float* __restrict__ out)
{
    extern __shared__ unsigned char smem_raw[];
    Smem& s = *reinterpret_cast<Smem*>(smem_raw);
    const int cta = blockIdx.x;
    const int tid = threadIdx.x;
    const int lane = tid & 31, wrp = tid >> 5;

    float* out_O = out;
    float* out_h = out + (size_t)BB * TT * OUTD;
    float* out_c = out_h + BB * HHD;

    if (tid == 0) {
        s.base_u  = ld_acq(&g_flags[cta * 32]);
        s.rbase_u = ld_acq(&g_rflags[0]);
    }

    const bool is_mem = (cta < NMEM);
    const int gi = cta - NMEM;                         // 0..111 for gemm CTAs
    const int cnt   = (gi < 64) ? 5 : 4;               // h-indices owned
    const int hbase = (gi < 64) ? gi * 5 : 320 + (gi - 64) * 4;

    // ---------------- init ----------------
    if (!is_mem) {
        GemmS& G = s.u.g;
        // weight slice, K order [x(64) | h(512) | r(40)], zero-pad rows/cols
        for (int idx = tid; idx < RWS * KPAD; idx += NTHR) {
            int lr = idx / KPAD, k = idx - lr * KPAD;
            int g = lr & 3, hl = lr >> 2;
            float v = 0.f;
            if (hl < cnt) {
                int gr = g * HHD + hbase + hl;
                if (k < IND)             v = W_ih[gr * (IND + MMD) + k];
                else if (k < IND + HHD)  v = W_hh[gr * HHD + (k - IND)];
                else if (k < KTOT)       v = W_ih[gr * (IND + MMD) + IND + (k - IND - HHD)];
            }
            G.W[idx] = v;
        }
        if (tid < RWS) {
            int g = tid & 3, hl = tid >> 2;
            G.bias[tid] = (hl < cnt)
                ? (b_ih[g * HHD + hbase + hl] + b_hh[g * HHD + hbase + hl]) : 0.f;
        }
        if (tid < 5 * BB) {
            int b = tid / 5, hl = tid - b * 5;
            G.cst[hl * BB + b] = (hl < cnt) ? c0[b * HHD + hbase + hl] : 0.f;
        }
        // stage step-0 input [x0 | h0 | r0 | pad]
        for (int idx = tid; idx < BB * KPAD; idx += NTHR) {
            int b = idx / KPAD, k = idx - b * KPAD;
            float v = 0.f;
            if (k < IND)             v = x[(b * TT) * IND + k];
            else if (k < IND + HHD)  v = h0[b * HHD + (k - IND)];
            else if (k < KTOT)       v = r0_[b * MMD + (k - IND - HHD)];
            G.inp[idx] = v;
        }
        __syncthreads();
        gemm_xh(G, tid);               // xh partials for t = 0
    } else {
        MemS& M = s.u.m;
        for (int idx = tid; idx < RCACHE * HHD; idx += NTHR) {
            int r = idx >> 9, k = idx & (HHD - 1);
            M.pw[idx] = prow(r, W_k, W_b, W_e, W_a)[k];
        }
        for (int idx = tid; idx < NND * MMD; idx += NTHR) {
            int n = idx / MMD, m = idx - n * MMD;
            M.mem[n * 41 + m] = mem0[cta * NND * MMD + idx];
        }
    }
    __syncthreads();
    const unsigned rb0 = s.rbase_u;
    unsigned barc = s.base_u;

    for (int t = 0; t < TT; t++) {
        const int hp = t & 1;

        // ========== part 1 (gemm CTAs): finish gates with r(t-1) -> h(t) ==========
        if (!is_mem) {
            GemmS& G = s.u.g;
            if (t > 0) {
                if (wrp == 0) {
                    unsigned tgt = rb0 + (unsigned)t;
                    for (;;) {
                        bool ok = true;
                        if (lane < NMEM)
                            ok = ((int)(ld_acq(&g_rflags[lane * 32]) - tgt) >= 0);
                        if (__all_sync(0xffffffffu, ok)) break;
                    }
                }
                __syncthreads();
                if (tid < 160) {       // stage r(t-1) into inp f4 slots 144..153
                    int b = tid / 10, q = tid - b * 10;
                    const float4* gr4 =
                        reinterpret_cast<const float4*>(&g_r[hp ^ 1][b][0]);
                    reinterpret_cast<float4*>(G.inp)[b * KP4 + 144 + q] =
                        __ldcg(gr4 + q);
                }
                __syncthreads();
            }
            // r-part (40 dims) folded into red by first 64 threads
            if (tid < 64) {
                const int kc = tid >> 4, tile = tid & 15;
                const int rg = tile & 3, bg = tile >> 2;
                const int roff = (kc < 2) ? 144 + kc * 3 : 150 + (kc - 2) * 2;
                const int rlen = (kc < 2) ? 3 : 2;
                const float4* W4 = reinterpret_cast<const float4*>(G.W);
                const float4* I4 = reinterpret_cast<const float4*>(G.inp);
                float a[20];
                float* rb = &G.red[(kc * 16 + tile) * RWS];
                #pragma unroll
                for (int q = 0; q < 20; q++) a[q] = rb[q];
                #pragma unroll 3
                for (int q = 0; q < rlen; q++) {
                    float4 wv[5], iv[4];
                    #pragma unroll
                    for (int i = 0; i < 5; i++)
                        wv[i] = W4[(rg + 4 * i) * KP4 + roff + q];
                    #pragma unroll
                    for (int j = 0; j < 4; j++)
                        iv[j] = I4[(bg + 4 * j) * KP4 + roff + q];
                    #pragma unroll
                    for (int i = 0; i < 5; i++) {
                        #pragma unroll
                        for (int j = 0; j < 4; j++) { DOT4(a[i * 4 + j], wv[i], iv[j]) }
                    }
                }
                #pragma unroll
                for (int q = 0; q < 20; q++) rb[q] = a[q];
            }
            __syncthreads();
            if (tid < RWS * BB) {      // reduce split-K
                int b = tid / RWS, lr = tid - b * RWS;
                int tile = (b & 3) * 4 + (lr & 3);
                int cell = (lr >> 2) * 4 + (b >> 2);
                float v = G.bias[lr];
                #pragma unroll
                for (int kc2 = 0; kc2 < 32; kc2++)
                    v += G.red[(kc2 * 16 + tile) * RWS + cell];
                G.gate[lr * BB + b] = v;
            }
            __syncthreads();
            if (tid < 5 * BB) {        // LSTM pointwise -> h(t)
                int b = tid / 5, hl = tid - b * 5;
                if (hl < cnt) {
                    float gv_i = G.gate[(0 + 4 * hl) * BB + b];
                    float gv_f = G.gate[(1 + 4 * hl) * BB + b];
                    float gv_g = G.gate[(2 + 4 * hl) * BB + b];
                    float gv_o = G.gate[(3 + 4 * hl) * BB + b];
                    float iv = 1.f / (1.f + expf(-gv_i));
                    float fv = 1.f / (1.f + expf(-gv_f));
                    float gv = tanhf(gv_g);
                    float ov = 1.f / (1.f + expf(-gv_o));
                    float cn = fv * G.cst[hl * BB + b] + iv * gv;
                    float hn = ov * tanhf(cn);
                    G.cst[hl * BB + b] = cn;
                    g_h[hp][b][hbase + hl] = hn;
                    if (t == TT - 1) {
                        out_h[b * HHD + hbase + hl] = hn;
                        out_c[b * HHD + hbase + hl] = cn;
                    }
                }
            }
        }
        grid_barrier(cta, ++barc);

        // ========== window B ==========
        if (is_mem) {
            if (t < TT - 1) {
                MemS& M = s.u.m;
                const int b = cta;
                {   // 121-row projection GEMV over h(t)
                    const float4* h4 =
                        reinterpret_cast<const float4*>(&g_h[hp][b][0]);
                    float4 hv0 = __ldcg(h4 + lane);
                    float4 hv1 = __ldcg(h4 + lane + 32);
                    float4 hv2 = __ldcg(h4 + lane + 64);
                    float4 hv3 = __ldcg(h4 + lane + 96);
                    #pragma unroll
                    for (int jr = 0; jr < 8; jr++) {
                        int r = wrp + 16 * jr;
                        if (r <= 120) {
                            float4 a0, a1, a2, a3;
                            if (r < RCACHE) {
                                const float4* w4 =
                                    reinterpret_cast<const float4*>(&M.pw[r * HHD]);
                                a0 = w4[lane];      a1 = w4[lane + 32];
                                a2 = w4[lane + 64]; a3 = w4[lane + 96];
                            } else {
                                const float4* w4 = reinterpret_cast<const float4*>(
                                    prow(r, W_k, W_b, W_e, W_a));
                                a0 = __ldg(w4 + lane);      a1 = __ldg(w4 + lane + 32);
                                a2 = __ldg(w4 + lane + 64); a3 = __ldg(w4 + lane + 96);
                            }
                            float acc = 0.f;
                            DOT4(acc, a0, hv0) DOT4(acc, a1, hv1)
                            DOT4(acc, a2, hv2) DOT4(acc, a3, hv3)
                            #pragma unroll
                            for (int off = 16; off; off >>= 1)
                                acc += __shfl_xor_sync(0xffffffffu, acc, off);
                            if (lane == 0) M.proj[r] = acc;
                        }
                    }
                }
                __syncthreads();
                if (tid < 121) {
                    float v = M.proj[tid];
                    if (tid < 40) {
                        M.key[tid] = tanhf(v + b_k[tid]);
                    } else if (tid == 40) {
                        float zz = v + b_b[0];
                        M.scal[1] = fmaxf(zz, 0.f) + log1pf(expf(-fabsf(zz))) + EPSV;
                    } else if (tid <= 80) {
                        int m = tid - 41;
                        M.ev[m] = 1.f / (1.f + expf(-(v + b_e[m])));
                    } else {
                        int m = tid - 81;
                        M.av[m] = tanhf(v + b_a[m]);
                    }
                }
                __syncthreads();
                if (tid < NND) {
                    const float* mr = &M.mem[tid * 41];
                    float dot = 0.f, nrm = 0.f;
                    #pragma unroll
                    for (int m = 0; m < MMD; m++) {
                        float mv = mr[m];
                        dot += mv * M.key[m];
                        nrm += mv * mv;
                    }
                    M.z[tid] = dot / (sqrtf(nrm) + EPSV);
                } else if (wrp == 8) {
                    float v = 0.f;
                    if (lane < MMD)      { float kv = M.key[lane];      v  = kv * kv; }
                    if (lane + 32 < MMD) { float kv = M.key[lane + 32]; v += kv * kv; }
                    #pragma unroll
                    for (int off = 16; off; off >>= 1)
                        v += __shfl_xor_sync(0xffffffffu, v, off);
                    if (lane == 0) M.scal[0] = sqrtf(v) + EPSV;
                }
                __syncthreads();
                if (wrp == 0) {        // softmax, one warp, 4 entries/lane
                    float bscale = M.scal[1] / M.scal[0];
                    float z0 = M.z[lane]      * bscale;
                    float z1 = M.z[lane + 32] * bscale;
                    float z2 = M.z[lane + 64] * bscale;
                    float z3 = M.z[lane + 96] * bscale;
                    float mx = fmaxf(fmaxf(z0, z1), fmaxf(z2, z3));
                    #pragma unroll
                    for (int off = 16; off; off >>= 1)
                        mx = fmaxf(mx, __shfl_xor_sync(0xffffffffu, mx, off));
                    float e0 = expf(z0 - mx), e1 = expf(z1 - mx);
                    float e2 = expf(z2 - mx), e3 = expf(z3 - mx);
                    float sv = e0 + e1 + e2 + e3;
                    #pragma unroll
                    for (int off = 16; off; off >>= 1)
                        sv += __shfl_xor_sync(0xffffffffu, sv, off);
                    float inv = 1.f / sv;
                    M.wsm[lane]      = e0 * inv;
                    M.wsm[lane + 32] = e1 * inv;
                    M.wsm[lane + 64] = e2 * inv;
                    M.wsm[lane + 96] = e3 * inv;
                }
                __syncthreads();
                if (tid < NND) {       // erase/add
                    float wv = M.wsm[tid];
                    float* mr = &M.mem[tid * 41];
                    #pragma unroll
                    for (int m = 0; m < MMD; m++)
                        mr[m] = mr[m] * (1.f - wv * M.ev[m]) + wv * M.av[m];
                }
                __syncthreads();
                if (tid < 320) {       // read r = w^T M, partials
                    int m = tid >> 3, p = tid & 7;
                    float sv = 0.f;
                    #pragma unroll
                    for (int n = p * 16; n < p * 16 + 16; n++)
                        sv += M.wsm[n] * M.mem[n * 41 + m];
                    M.rred[tid] = sv;
                }
                __syncthreads();
                if (tid < MMD) {
                    float sv = 0.f;
                    #pragma unroll
                    for (int p = 0; p < 8; p++) sv += M.rred[tid * 8 + p];
                    g_r[hp][b][tid] = sv;
                }
                __syncthreads();
                if (tid == 0) {
                    __threadfence();
                    st_rel(&g_rflags[cta * 32], rb0 + (unsigned)(t + 1));
                }
            }
        } else {
            GemmS& G = s.u.g;
            // prestage x(t+1) and h(t)
            for (int idx = tid; idx < BB * (IND + HHD); idx += NTHR) {
                int b = idx / (IND + HHD), k = idx - b * (IND + HHD);
                if (k < IND) {
                    if (t + 1 < TT)
                        G.inp[b * KPAD + k] = x[(b * TT + t + 1) * IND + k];
                } else {
                    G.inp[b * KPAD + k] = __ldcg(&g_h[hp][b][k - IND]);
                }
            }
            __syncthreads();
            {   // fc(t) from staged h in smem
                int grp = tid >> 4, l16 = tid & 15;
                int d = gi + NGEMM * grp;
                bool valid = (d < 1024);
                int d2 = valid ? d : 0;
                int b = d2 >> 6, row = d2 & 63;
                const float4* w4 =
                    reinterpret_cast<const float4*>(W_fc + row * HHD);
                const float4* h4 =
                    reinterpret_cast<const float4*>(G.inp) + b * KP4 + 16;
                float acc = 0.f;
                #pragma unroll
                for (int q = 0; q < 8; q++) {
                    float4 wv = __ldg(w4 + l16 + 16 * q);
                    float4 hv = h4[l16 + 16 * q];
                    DOT4(acc, wv, hv)
                }
                #pragma unroll
                for (int off = 8; off; off >>= 1)
                    acc += __shfl_xor_sync(0xffffffffu, acc, off);
                if (valid && l16 == 0)
                    out_O[(b * TT + t) * OUTD + row] = tanhf(acc + b_fc[row]);
            }
            if (t + 1 < TT) gemm_xh(G, tid);   // xh partials for t+1
        }
    }
}

extern "C" void kernel_launch(void* const* d_in, const int* in_sizes, int n_in,
                              void* d_out, int out_size) {
    (void)in_sizes; (void)n_in; (void)out_size;
    cudaFuncSetAttribute(ntm_kernel,
                         cudaFuncAttributeMaxDynamicSharedMemorySize,
                         (int)sizeof(Smem));
    ntm_kernel<<<NCTA, NTHR, sizeof(Smem)>>>(
        (const float*)d_in[0],  (const float*)d_in[1],  (const float*)d_in[2],
        (const float*)d_in[3],  (const float*)d_in[4],  (const float*)d_in[5],
        (const float*)d_in[6],  (const float*)d_in[7],  (const float*)d_in[8],
        (const float*)d_in[9],  (const float*)d_in[10], (const float*)d_in[11],
        (const float*)d_in[12], (const float*)d_in[13], (const float*)d_in[14],
        (const float*)d_in[15], (const float*)d_in[16], (const float*)d_in[17],
        (const float*)d_in[18], (float*)d_out);
}

// round 7
// speedup vs baseline: 2.4552x; 1.1524x over previous
#include <cuda_runtime.h>
#include <math.h>

#define BB 16
#define TT 1024
#define IND 64
#define OUTD 64
#define HHD 512
#define NND 128
#define MMD 40
#define KTOT 616        // IND + HHD + MMD, order [x|h|r]
#define KP4  157        // padded row stride in float4
#define KPAD 628
#define NCTA 128
#define NMEM 16
#define NGEMM 112
#define NTHR 512
#define RWS 20          // gate rows per gemm CTA
#define EPSV 1e-8f
#define RCACHE 80       // projection rows cached in smem (of 121)

// ---------------- persistent global state ----------------
__device__ __align__(16) float g_h[2][BB][HHD];
__device__ __align__(16) float g_r[2][BB][MMD];
__device__ unsigned g_hflags[NGEMM * 32];  // h(t)-ready, one per gemm CTA
__device__ unsigned g_rflags[NMEM * 32];   // r(t)-ready, one per mem CTA
__device__ unsigned g_gen = 0;             // launch generation

static __device__ __forceinline__ unsigned ld_acq(const unsigned* p) {
    unsigned v;
    asm volatile("ld.acquire.gpu.global.u32 %0, [%1];" : "=r"(v) : "l"(p) : "memory");
    return v;
}
static __device__ __forceinline__ void st_rel(unsigned* p, unsigned v) {
    asm volatile("st.release.gpu.global.u32 [%0], %1;" :: "l"(p), "r"(v) : "memory");
}

// Wait until all NGEMM h-flags >= k. Warp 0 polls, then CTA-wide sync.
static __device__ __forceinline__ void wait_hflags(unsigned k) {
    if (threadIdx.x < 32) {
        for (;;) {
            bool ok = true;
            #pragma unroll
            for (int q = 0; q < 4; q++) {
                int f = threadIdx.x + 32 * q;
                if (f < NGEMM)
                    ok &= ((int)(ld_acq(&g_hflags[f * 32]) - k) >= 0);
            }
            if (__all_sync(0xffffffffu, ok)) break;
        }
    }
    __syncthreads();
}

struct __align__(16) GemmS {
    alignas(16) float W[RWS * KPAD];       // gate-weight slice [x|h|r]
    alignas(16) float inp[BB * KPAD];      // staged [x|h|r]
    alignas(16) float red[32 * 16 * RWS];  // split-K partials
    float gate[RWS * BB];
    float bias[RWS];
    float cst[5 * BB];
};
struct __align__(16) MemS {
    alignas(16) float pw[RCACHE * HHD];    // projection weight rows
    float mem[NND * 41];
    float rred[320];
    float proj[NND];
    float key[MMD];
    float ev[MMD];
    float av[MMD];
    float z[NND];
    float wsm[NND];
    float scal[4];                         // [0]=||key||+eps, [1]=beta
};
struct __align__(16) Smem {
    union { GemmS g; MemS m; } u;
    unsigned genv;
};

static __device__ __forceinline__ const float* prow(int r,
    const float* W_k, const float* W_b, const float* W_e, const float* W_a)
{
    if (r < 40)  return W_k + r * HHD;
    if (r == 40) return W_b;
    if (r <= 80) return W_e + (r - 41) * HHD;
    return W_a + (r - 81) * HHD;
}

#define DOT4(acc, wv, iv) \
    acc += wv.x*iv.x; acc += wv.y*iv.y; acc += wv.z*iv.z; acc += wv.w*iv.w;

// xh-part GEMM (576 dims = f4 0..143), conflict-free interleaved mapping.
static __device__ __forceinline__ void gemm_xh(GemmS& G, int tid) {
    const int kc = tid >> 4, tile = tid & 15;
    const int rg = tile & 3, bg = tile >> 2;
    const int koff = (kc < 16) ? kc * 5 : 80 + (kc - 16) * 4;
    const int klen = (kc < 16) ? 5 : 4;
    const float4* W4 = reinterpret_cast<const float4*>(G.W);
    const float4* I4 = reinterpret_cast<const float4*>(G.inp);
    float a[20];
    #pragma unroll
    for (int q = 0; q < 20; q++) a[q] = 0.f;
    #pragma unroll 5
    for (int q = 0; q < klen; q++) {
        float4 wv[5], iv[4];
        #pragma unroll
        for (int i = 0; i < 5; i++) wv[i] = W4[(rg + 4 * i) * KP4 + koff + q];
        #pragma unroll
        for (int j = 0; j < 4; j++) iv[j] = I4[(bg + 4 * j) * KP4 + koff + q];
        #pragma unroll
        for (int i = 0; i < 5; i++) {
            #pragma unroll
            for (int j = 0; j < 4; j++) { DOT4(a[i * 4 + j], wv[i], iv[j]) }
        }
    }
    float* rb = &G.red[(kc * 16 + tile) * RWS];
    #pragma unroll
    for (int q = 0; q < 20; q++) rb[q] = a[q];
}

__global__ void __launch_bounds__(NTHR, 1) ntm_kernel(
    const float* __restrict__ x,    const float* __restrict__ h0,
    const float* __restrict__ c0,   const float* __restrict__ mem0,
    const float* __restrict__ r0_,  const float* __restrict__ W_ih,
    const float* __restrict__ b_ih, const float* __restrict__ W_hh,
    const float* __restrict__ b_hh, const float* __restrict__ W_fc,
    const float* __restrict__ b_fc, const float* __restrict__ W_e,
    const float* __restrict__ b_e,  const float* __restrict__ W_a,
    const float* __restrict__ b_a,  const float* __restrict__ W_k,
    const float* __restrict__ b_k,  const float* __restrict__ W_b,
    const float* __restrict__ b_b,  float* __restrict__ out)
{
    extern __shared__ unsigned char smem_raw[];
    Smem& s = *reinterpret_cast<Smem*>(smem_raw);
    const int cta = blockIdx.x;
    const int tid = threadIdx.x;
    const int lane = tid & 31, wrp = tid >> 5;

    float* out_O = out;
    float* out_h = out + (size_t)BB * TT * OUTD;
    float* out_c = out_h + BB * HHD;

    if (tid == 0) s.genv = ld_acq(&g_gen);

    const bool is_mem = (cta < NMEM);
    const int gi = cta - NMEM;
    const int cnt   = (gi < 64) ? 5 : 4;
    const int hbase = (gi < 64) ? gi * 5 : 320 + (gi - 64) * 4;

    // ---------------- init ----------------
    if (!is_mem) {
        GemmS& G = s.u.g;
        for (int idx = tid; idx < RWS * KPAD; idx += NTHR) {
            int lr = idx / KPAD, k = idx - lr * KPAD;
            int g = lr & 3, hl = lr >> 2;
            float v = 0.f;
            if (hl < cnt) {
                int gr = g * HHD + hbase + hl;
                if (k < IND)             v = W_ih[gr * (IND + MMD) + k];
                else if (k < IND + HHD)  v = W_hh[gr * HHD + (k - IND)];
                else if (k < KTOT)       v = W_ih[gr * (IND + MMD) + IND + (k - IND - HHD)];
            }
            G.W[idx] = v;
        }
        if (tid < RWS) {
            int g = tid & 3, hl = tid >> 2;
            G.bias[tid] = (hl < cnt)
                ? (b_ih[g * HHD + hbase + hl] + b_hh[g * HHD + hbase + hl]) : 0.f;
        }
        if (tid < 5 * BB) {
            int b = tid / 5, hl = tid - b * 5;
            G.cst[hl * BB + b] = (hl < cnt) ? c0[b * HHD + hbase + hl] : 0.f;
        }
        for (int idx = tid; idx < BB * KPAD; idx += NTHR) {
            int b = idx / KPAD, k = idx - b * KPAD;
            float v = 0.f;
            if (k < IND)             v = x[(b * TT) * IND + k];
            else if (k < IND + HHD)  v = h0[b * HHD + (k - IND)];
            else if (k < KTOT)       v = r0_[b * MMD + (k - IND - HHD)];
            G.inp[idx] = v;
        }
        __syncthreads();
        gemm_xh(G, tid);               // xh partials for t = 0
    } else {
        MemS& M = s.u.m;
        for (int idx = tid; idx < RCACHE * HHD; idx += NTHR) {
            int r = idx >> 9, k = idx & (HHD - 1);
            M.pw[idx] = prow(r, W_k, W_b, W_e, W_a)[k];
        }
        for (int idx = tid; idx < NND * MMD; idx += NTHR) {
            int n = idx / MMD, m = idx - n * MMD;
            M.mem[n * 41 + m] = mem0[cta * NND * MMD + idx];
        }
    }
    __syncthreads();
    const unsigned gen = s.genv;
    const unsigned hb0 = gen * (unsigned)TT;        // h-flag base this launch
    const unsigned rb0 = gen * (unsigned)(TT - 1);  // r-flag base this launch

    if (is_mem) {
        // =================== memory CTA loop ===================
        MemS& M = s.u.m;
        const int b = cta;
        for (int t = 0; t < TT - 1; t++) {
            const int hp = t & 1;
            wait_hflags(hb0 + (unsigned)(t + 1));
            {   // 121-row projection GEMV over h(t)
                const float4* h4 = reinterpret_cast<const float4*>(&g_h[hp][b][0]);
                float4 hv0 = __ldcg(h4 + lane);
                float4 hv1 = __ldcg(h4 + lane + 32);
                float4 hv2 = __ldcg(h4 + lane + 64);
                float4 hv3 = __ldcg(h4 + lane + 96);
                #pragma unroll
                for (int jr = 0; jr < 8; jr++) {
                    int r = wrp + 16 * jr;
                    if (r <= 120) {
                        float4 a0, a1, a2, a3;
                        if (r < RCACHE) {
                            const float4* w4 =
                                reinterpret_cast<const float4*>(&M.pw[r * HHD]);
                            a0 = w4[lane];      a1 = w4[lane + 32];
                            a2 = w4[lane + 64]; a3 = w4[lane + 96];
                        } else {
                            const float4* w4 = reinterpret_cast<const float4*>(
                                prow(r, W_k, W_b, W_e, W_a));
                            a0 = __ldg(w4 + lane);      a1 = __ldg(w4 + lane + 32);
                            a2 = __ldg(w4 + lane + 64); a3 = __ldg(w4 + lane + 96);
                        }
                        float acc = 0.f;
                        DOT4(acc, a0, hv0) DOT4(acc, a1, hv1)
                        DOT4(acc, a2, hv2) DOT4(acc, a3, hv3)
                        #pragma unroll
                        for (int off = 16; off; off >>= 1)
                            acc += __shfl_xor_sync(0xffffffffu, acc, off);
                        if (lane == 0) M.proj[r] = acc;
                    }
                }
            }
            __syncthreads();
            if (tid < 121) {
                float v = M.proj[tid];
                if (tid < 40) {
                    M.key[tid] = tanhf(v + b_k[tid]);
                } else if (tid == 40) {
                    float zz = v + b_b[0];
                    M.scal[1] = fmaxf(zz, 0.f) + log1pf(expf(-fabsf(zz))) + EPSV;
                } else if (tid <= 80) {
                    int m = tid - 41;
                    M.ev[m] = 1.f / (1.f + expf(-(v + b_e[m])));
                } else {
                    int m = tid - 81;
                    M.av[m] = tanhf(v + b_a[m]);
                }
            }
            __syncthreads();
            if (tid < NND) {
                const float* mr = &M.mem[tid * 41];
                float dot = 0.f, nrm = 0.f;
                #pragma unroll
                for (int m = 0; m < MMD; m++) {
                    float mv = mr[m];
                    dot += mv * M.key[m];
                    nrm += mv * mv;
                }
                M.z[tid] = dot / (sqrtf(nrm) + EPSV);
            } else if (wrp == 8) {
                float v = 0.f;
                if (lane < MMD)      { float kv = M.key[lane];      v  = kv * kv; }
                if (lane + 32 < MMD) { float kv = M.key[lane + 32]; v += kv * kv; }
                #pragma unroll
                for (int off = 16; off; off >>= 1)
                    v += __shfl_xor_sync(0xffffffffu, v, off);
                if (lane == 0) M.scal[0] = sqrtf(v) + EPSV;
            }
            __syncthreads();
            if (wrp == 0) {            // softmax, one warp
                float bscale = M.scal[1] / M.scal[0];
                float z0 = M.z[lane]      * bscale;
                float z1 = M.z[lane + 32] * bscale;
                float z2 = M.z[lane + 64] * bscale;
                float z3 = M.z[lane + 96] * bscale;
                float mx = fmaxf(fmaxf(z0, z1), fmaxf(z2, z3));
                #pragma unroll
                for (int off = 16; off; off >>= 1)
                    mx = fmaxf(mx, __shfl_xor_sync(0xffffffffu, mx, off));
                float e0 = expf(z0 - mx), e1 = expf(z1 - mx);
                float e2 = expf(z2 - mx), e3 = expf(z3 - mx);
                float sv = e0 + e1 + e2 + e3;
                #pragma unroll
                for (int off = 16; off; off >>= 1)
                    sv += __shfl_xor_sync(0xffffffffu, sv, off);
                float inv = 1.f / sv;
                M.wsm[lane]      = e0 * inv;
                M.wsm[lane + 32] = e1 * inv;
                M.wsm[lane + 64] = e2 * inv;
                M.wsm[lane + 96] = e3 * inv;
            }
            __syncthreads();
            if (tid < NND) {           // erase/add
                float wv = M.wsm[tid];
                float* mr = &M.mem[tid * 41];
                #pragma unroll
                for (int m = 0; m < MMD; m++)
                    mr[m] = mr[m] * (1.f - wv * M.ev[m]) + wv * M.av[m];
            }
            __syncthreads();
            if (tid < 320) {           // read r = w^T M, partials
                int m = tid >> 3, p = tid & 7;
                float sv = 0.f;
                #pragma unroll
                for (int n = p * 16; n < p * 16 + 16; n++)
                    sv += M.wsm[n] * M.mem[n * 41 + m];
                M.rred[tid] = sv;
            }
            __syncthreads();
            if (tid < MMD) {
                float sv = 0.f;
                #pragma unroll
                for (int p = 0; p < 8; p++) sv += M.rred[tid * 8 + p];
                g_r[hp][b][tid] = sv;
            }
            __syncthreads();
            if (tid == 0) {
                __threadfence();
                st_rel(&g_rflags[cta * 32], rb0 + (unsigned)(t + 1));
            }
        }
    } else {
        // =================== gemm CTA loop ===================
        GemmS& G = s.u.g;
        for (int t = 0; t < TT; t++) {
            const int hp = t & 1;
            // ---- part 1: finish gates with r(t-1) -> h(t) ----
            if (t > 0) {
                if (wrp == 0) {
                    unsigned tgt = rb0 + (unsigned)t;
                    for (;;) {
                        bool ok = true;
                        if (lane < NMEM)
                            ok = ((int)(ld_acq(&g_rflags[lane * 32]) - tgt) >= 0);
                        if (__all_sync(0xffffffffu, ok)) break;
                    }
                }
                __syncthreads();
                if (tid < 160) {       // stage r(t-1) into inp f4 slots 144..153
                    int b = tid / 10, q = tid - b * 10;
                    const float4* gr4 =
                        reinterpret_cast<const float4*>(&g_r[hp ^ 1][b][0]);
                    reinterpret_cast<float4*>(G.inp)[b * KP4 + 144 + q] =
                        __ldcg(gr4 + q);
                }
                __syncthreads();
            }
            if (tid < 64) {            // r-part (40 dims) folded into red
                const int kc = tid >> 4, tile = tid & 15;
                const int rg = tile & 3, bg = tile >> 2;
                const int roff = (kc < 2) ? 144 + kc * 3 : 150 + (kc - 2) * 2;
                const int rlen = (kc < 2) ? 3 : 2;
                const float4* W4 = reinterpret_cast<const float4*>(G.W);
                const float4* I4 = reinterpret_cast<const float4*>(G.inp);
                float a[20];
                float* rb = &G.red[(kc * 16 + tile) * RWS];
                #pragma unroll
                for (int q = 0; q < 20; q++) a[q] = rb[q];
                #pragma unroll 3
                for (int q = 0; q < rlen; q++) {
                    float4 wv[5], iv[4];
                    #pragma unroll
                    for (int i = 0; i < 5; i++)
                        wv[i] = W4[(rg + 4 * i) * KP4 + roff + q];
                    #pragma unroll
                    for (int j = 0; j < 4; j++)
                        iv[j] = I4[(bg + 4 * j) * KP4 + roff + q];
                    #pragma unroll
                    for (int i = 0; i < 5; i++) {
                        #pragma unroll
                        for (int j = 0; j < 4; j++) { DOT4(a[i * 4 + j], wv[i], iv[j]) }
                    }
                }
                #pragma unroll
                for (int q = 0; q < 20; q++) rb[q] = a[q];
            }
            __syncthreads();
            if (tid < RWS * BB) {      // reduce split-K
                int b = tid / RWS, lr = tid - b * RWS;
                int tile = (b & 3) * 4 + (lr & 3);
                int cell = (lr >> 2) * 4 + (b >> 2);
                float v = G.bias[lr];
                #pragma unroll
                for (int kc2 = 0; kc2 < 32; kc2++)
                    v += G.red[(kc2 * 16 + tile) * RWS + cell];
                G.gate[lr * BB + b] = v;
            }
            __syncthreads();
            if (tid < 5 * BB) {        // LSTM pointwise -> h(t)
                int b = tid / 5, hl = tid - b * 5;
                if (hl < cnt) {
                    float gv_i = G.gate[(0 + 4 * hl) * BB + b];
                    float gv_f = G.gate[(1 + 4 * hl) * BB + b];
                    float gv_g = G.gate[(2 + 4 * hl) * BB + b];
                    float gv_o = G.gate[(3 + 4 * hl) * BB + b];
                    float iv = 1.f / (1.f + expf(-gv_i));
                    float fv = 1.f / (1.f + expf(-gv_f));
                    float gv = tanhf(gv_g);
                    float ov = 1.f / (1.f + expf(-gv_o));
                    float cn = fv * G.cst[hl * BB + b] + iv * gv;
                    float hn = ov * tanhf(cn);
                    G.cst[hl * BB + b] = cn;
                    g_h[hp][b][hbase + hl] = hn;
                    if (t == TT - 1) {
                        out_h[b * HHD + hbase + hl] = hn;
                        out_c[b * HHD + hbase + hl] = cn;
                    }
                }
            }
            __syncthreads();
            if (tid == 0) {
                __threadfence();
                st_rel(&g_hflags[gi * 32], hb0 + (unsigned)(t + 1));
            }
            // ---- window B: prestage, fc(t), xh-gemm for t+1 ----
            wait_hflags(hb0 + (unsigned)(t + 1));
            for (int idx = tid; idx < BB * 144; idx += NTHR) {
                int b = idx / 144, q = idx - b * 144;
                float4 v;
                if (q < 16) {
                    v = (t + 1 < TT)
                        ? __ldg(reinterpret_cast<const float4*>(
                              &x[(b * TT + t + 1) * IND]) + q)
                        : make_float4(0.f, 0.f, 0.f, 0.f);
                } else {
                    v = __ldcg(reinterpret_cast<const float4*>(&g_h[hp][b][0])
                               + (q - 16));
                }
                reinterpret_cast<float4*>(G.inp)[b * KP4 + q] = v;
            }
            __syncthreads();
            {   // fc(t) from staged h
                int grp = tid >> 4, l16 = tid & 15;
                int d = gi + NGEMM * grp;
                bool valid = (d < 1024);
                int d2 = valid ? d : 0;
                int b = d2 >> 6, row = d2 & 63;
                const float4* w4 =
                    reinterpret_cast<const float4*>(W_fc + row * HHD);
                const float4* h4 =
                    reinterpret_cast<const float4*>(G.inp) + b * KP4 + 16;
                float acc = 0.f;
                #pragma unroll
                for (int q = 0; q < 8; q++) {
                    float4 wv = __ldg(w4 + l16 + 16 * q);
                    float4 hv = h4[l16 + 16 * q];
                    DOT4(acc, wv, hv)
                }
                #pragma unroll
                for (int off = 8; off; off >>= 1)
                    acc += __shfl_xor_sync(0xffffffffu, acc, off);
                if (valid && l16 == 0)
                    out_O[(b * TT + t) * OUTD + row] = tanhf(acc + b_fc[row]);
            }
            if (t + 1 < TT) gemm_xh(G, tid);
        }
        if (cta == NCTA - 1 && tid == 0) {
            st_rel(&g_gen, gen + 1);   // next launch's flag base
        }
    }
}

extern "C" void kernel_launch(void* const* d_in, const int* in_sizes, int n_in,
                              void* d_out, int out_size) {
    (void)in_sizes; (void)n_in; (void)out_size;
    cudaFuncSetAttribute(ntm_kernel,
                         cudaFuncAttributeMaxDynamicSharedMemorySize,
                         (int)sizeof(Smem));
    ntm_kernel<<<NCTA, NTHR, sizeof(Smem)>>>(
        (const float*)d_in[0],  (const float*)d_in[1],  (const float*)d_in[2],
        (const float*)d_in[3],  (const float*)d_in[4],  (const float*)d_in[5],
        (const float*)d_in[6],  (const float*)d_in[7],  (const float*)d_in[8],
        (const float*)d_in[9],  (const float*)d_in[10], (const float*)d_in[11],
        (const float*)d_in[12], (const float*)d_in[13], (const float*)d_in[14],
        (const float*)d_in[15], (const float*)d_in[16], (const float*)d_in[17],
        (const float*)d_in[18], (float*)d_out);
}